// round 12
// baseline (speedup 1.0000x reference)
#include <cuda_runtime.h>
#include <cuda_fp16.h>
#include <cstdint>

// out[b,n] = sum_{c,hw} x[b,c,hw]*W_s[n,hw]*W_d[n,c] + W_b[n]
// GEMM Y[(b,c),n] = X[8192,3136] @ Ws[1024,3136]^T, single-fp16 mma.sync,
// fp32 accum, fused W_d epilogue, K-split 4 via atomicAdd merge.
// R11: BM 128->256 with 512 threads, 1 CTA/SM (full RF). Same 16 warps/SM
// as before but write traffic per HMMA drops 64->47B (R10 analysis: smem
// bytes co-bound with tensor at 2x128x128). 4-stage pipeline (192KB smem),
// prefetch distance 3, one __syncthreads per chunk.

#define K_DIM 3136
#define C_DIM 256
#define N_DIM 1024
#define M_DIM 8192
#define BM 256
#define BN 128
#define BK 64
#define KSPLIT 4
#define MAT_A 32768           // A: 256 rows * 128B
#define STAGE_B 49152         // A(32KB) + B(16KB)
#define NSTAGES 4
#define SMEM_TOTAL (NSTAGES * STAGE_B)   // 196608

// ---------------- scratch (alloc-free) ----------------
__device__ __align__(256) __half g_X16[(long)M_DIM * K_DIM];
__device__ __align__(256) __half g_W16[(long)N_DIM * K_DIM];

__device__ __forceinline__ uint32_t smem_u32(const void* p) {
    uint32_t a;
    asm("{ .reg .u64 t; cvta.to.shared.u64 t, %1; cvt.u32.u64 %0, t; }"
        : "=r"(a) : "l"(p));
    return a;
}
__device__ __forceinline__ void cp_async16(uint32_t dst, const void* src) {
    asm volatile("cp.async.cg.shared.global [%0], [%1], 16;"
                 :: "r"(dst), "l"(src));
}
__device__ __forceinline__ void cp_commit() {
    asm volatile("cp.async.commit_group;" ::: "memory");
}
template <int N>
__device__ __forceinline__ void cp_wait() {
    asm volatile("cp.async.wait_group %0;" :: "n"(N) : "memory");
}
__device__ __forceinline__ void ldsm4(uint32_t& r0, uint32_t& r1, uint32_t& r2,
                                      uint32_t& r3, uint32_t a) {
    asm volatile("ldmatrix.sync.aligned.m8n8.x4.shared.b16 {%0,%1,%2,%3}, [%4];"
                 : "=r"(r0), "=r"(r1), "=r"(r2), "=r"(r3) : "r"(a));
}
__device__ __forceinline__ void mma16816(float* c, const uint32_t* a,
                                         const uint32_t* b) {
    asm volatile(
        "mma.sync.aligned.m16n8k16.row.col.f32.f16.f16.f32 "
        "{%0,%1,%2,%3}, {%4,%5,%6,%7}, {%8,%9}, {%0,%1,%2,%3};"
        : "+f"(c[0]), "+f"(c[1]), "+f"(c[2]), "+f"(c[3])
        : "r"(a[0]), "r"(a[1]), "r"(a[2]), "r"(a[3]), "r"(b[0]), "r"(b[1]));
}

// ---------------- fused convert (8 elem/thread, 16B stores) + bias init ----
__device__ __forceinline__ uint4 cvt8(const float* __restrict__ s) {
    float4 v0 = *(const float4*)s;
    float4 v1 = *(const float4*)(s + 4);
    __half2 h0 = __floats2half2_rn(v0.x, v0.y);
    __half2 h1 = __floats2half2_rn(v0.z, v0.w);
    __half2 h2 = __floats2half2_rn(v1.x, v1.y);
    __half2 h3 = __floats2half2_rn(v1.z, v1.w);
    uint4 r;
    r.x = *(const uint32_t*)&h0; r.y = *(const uint32_t*)&h1;
    r.z = *(const uint32_t*)&h2; r.w = *(const uint32_t*)&h3;
    return r;
}

__global__ void prep_kernel(const float* __restrict__ x,
                            const float* __restrict__ ws,
                            const float* __restrict__ wb,
                            float* __restrict__ out) {
    const long NX = (long)M_DIM * K_DIM;
    const long NW = (long)N_DIM * K_DIM;
    long i = ((long)blockIdx.x * blockDim.x + threadIdx.x) * 8;
    if (i < NX) {
        *(uint4*)(g_X16 + i) = cvt8(x + i);
    } else if (i < NX + NW) {
        long j = i - NX;
        *(uint4*)(g_W16 + j) = cvt8(ws + j);
    } else if (i < NX + NW + 32L * N_DIM) {
        long j = i - NX - NW;
        int nb = (int)(j & (N_DIM - 1));
        float4 b0 = *(const float4*)(wb + nb);
        float4 b1 = *(const float4*)(wb + nb + 4);
        *(float4*)(out + j) = b0;
        *(float4*)(out + j + 4) = b1;
    }
}

// ---------------- main GEMM ----------------
// smem swizzle: 16B chunk c of row r lives at r*128 + ((c ^ (r&7))<<4).
__global__ __launch_bounds__(512, 1)
void gemm_kernel(const float* __restrict__ Wd, float* __restrict__ out) {
    extern __shared__ char smem[];
    const uint32_t sb = smem_u32(smem);
    const int tid = threadIdx.x;
    const int lane = tid & 31;
    const int warp = tid >> 5;
    const int m0 = blockIdx.y * BM;
    const int n0 = blockIdx.x * BN;
    const int mwarp = (warp >> 2) * 64;   // 4 warp-rows: 0,64,128,192
    const int nwarp = (warp & 3) * 32;    // 4 warp-cols

    // K-split range: boundaries 0,13,25,37,49
    const int z = blockIdx.z;
    const int cs = (z == 0) ? 0 : 13 + 12 * (z - 1);
    const int nch = 13 + 12 * z - cs;

    float acc[4][4][4];
#pragma unroll
    for (int i = 0; i < 4; ++i)
#pragma unroll
        for (int j = 0; j < 4; ++j)
#pragma unroll
            for (int k = 0; k < 4; ++k) acc[i][j][k] = 0.f;

    const uint32_t e = (uint32_t)(lane & 7);          // swizzle key
    const uint32_t a_row = (uint32_t)(mwarp + (lane & 15)) * 128u;
    const uint32_t b_row =
        (uint32_t)(nwarp + (lane & 7) + ((lane >> 4) & 1) * 8) * 128u;
    uint32_t akoff[4], bkoff[4];
#pragma unroll
    for (int ks = 0; ks < 4; ++ks) {
        akoff[ks] = (((uint32_t)(ks * 2 + (lane >> 4)) ^ e) << 4);
        bkoff[ks] = (((uint32_t)(ks * 2 + ((lane >> 3) & 1)) ^ e) << 4);
    }

    // cp.async: A = 2048 16B chunks (u 0..3), B = 1024 (u 4..5)
    auto load_chunk = [&](int chunk, int s) {
        const long k0 = (long)chunk * BK;
        const uint32_t st = sb + (uint32_t)s * STAGE_B;
#pragma unroll
        for (int u = 0; u < 4; ++u) {
            const int lin = tid + u * 512;
            const int row = lin >> 3;
            const uint32_t c = (uint32_t)(lin & 7);
            const uint32_t soff =
                (uint32_t)(row * 128) + (((c ^ (uint32_t)(row & 7))) << 4);
            cp_async16(st + soff,
                       g_X16 + (long)(m0 + row) * K_DIM + k0 + c * 8);
        }
#pragma unroll
        for (int u = 0; u < 2; ++u) {
            const int lin = tid + u * 512;
            const int row = lin >> 3;
            const uint32_t c = (uint32_t)(lin & 7);
            const uint32_t soff =
                (uint32_t)(row * 128) + (((c ^ (uint32_t)(row & 7))) << 4);
            cp_async16(st + MAT_A + soff,
                       g_W16 + (long)(n0 + row) * K_DIM + k0 + c * 8);
        }
    };

    load_chunk(cs, 0); cp_commit();
    load_chunk(cs + 1, 1); cp_commit();
    load_chunk(cs + 2, 2); cp_commit();

    for (int i = 0; i < nch; ++i) {
        if (i + 3 <= nch - 1) cp_wait<2>();
        else if (i + 2 == nch) cp_wait<1>();
        else if (i + 1 == nch) cp_wait<0>();
        else cp_wait<2>();
        __syncthreads();   // chunk i visible; all warps done with chunk i-1
        if (i + 3 < nch) {
            load_chunk(cs + i + 3, (i + 3) & 3);
            cp_commit();
        }

        const uint32_t st = sb + (uint32_t)(i & 3) * STAGE_B;
        const uint32_t Ab = st + a_row;
        const uint32_t Bb = st + MAT_A + b_row;
#pragma unroll
        for (int ks = 0; ks < 4; ++ks) {
            uint32_t a[4][4], b[4][2];
#pragma unroll
            for (int mi = 0; mi < 4; ++mi)
                ldsm4(a[mi][0], a[mi][1], a[mi][2], a[mi][3],
                      Ab + (uint32_t)(mi * 16 * 128) + akoff[ks]);
#pragma unroll
            for (int seg = 0; seg < 2; ++seg)
                ldsm4(b[2 * seg][0], b[2 * seg][1], b[2 * seg + 1][0],
                      b[2 * seg + 1][1],
                      Bb + (uint32_t)(seg * 16 * 128) + bkoff[ks]);
#pragma unroll
            for (int mi = 0; mi < 4; ++mi)
#pragma unroll
                for (int ni = 0; ni < 4; ++ni)
                    mma16816(acc[mi][ni], a[mi], b[ni]);
        }
    }

    // ---------------- fused epilogue (partial over this z's K range) --------
    const int b = m0 >> 8;
    const int cbase = (m0 & (C_DIM - 1)) + mwarp;
    const int g = lane >> 2;
    const int t = lane & 3;

    float p[4][2];
#pragma unroll
    for (int ni = 0; ni < 4; ++ni) { p[ni][0] = 0.f; p[ni][1] = 0.f; }

#pragma unroll
    for (int mi = 0; mi < 4; ++mi) {
        const int c0 = cbase + mi * 16 + g;
#pragma unroll
        for (int ni = 0; ni < 4; ++ni) {
            const int n = n0 + nwarp + ni * 8 + 2 * t;
#pragma unroll
            for (int j = 0; j < 2; ++j) {
                const float w0 = __ldg(Wd + (long)(n + j) * C_DIM + c0);
                const float w1 = __ldg(Wd + (long)(n + j) * C_DIM + c0 + 8);
                p[ni][j] += acc[mi][ni][j] * w0 + acc[mi][ni][j + 2] * w1;
            }
        }
    }
#pragma unroll
    for (int ni = 0; ni < 4; ++ni)
#pragma unroll
        for (int j = 0; j < 2; ++j) {
#pragma unroll
            for (int mk = 4; mk <= 16; mk <<= 1)
                p[ni][j] += __shfl_xor_sync(0xFFFFFFFFu, p[ni][j], mk);
        }
    if (lane < 4) {
#pragma unroll
        for (int ni = 0; ni < 4; ++ni)
#pragma unroll
            for (int j = 0; j < 2; ++j)
                atomicAdd(out + (long)b * N_DIM + n0 + nwarp + ni * 8 + 2 * t + j,
                          p[ni][j]);
    }
}

extern "C" void kernel_launch(void* const* d_in, const int* in_sizes, int n_in,
                              void* d_out, int out_size) {
    const float* x  = (const float*)d_in[0];  // (32,256,56,56)
    const float* Ws = (const float*)d_in[1];  // (1024,56,56)
    const float* Wd = (const float*)d_in[2];  // (1024,256,1,1)
    const float* Wb = (const float*)d_in[3];  // (1,1024)
    float* out = (float*)d_out;               // (32,1024)

    cudaFuncSetAttribute(gemm_kernel,
                         cudaFuncAttributeMaxDynamicSharedMemorySize, SMEM_TOTAL);

    const long total =
        (long)M_DIM * K_DIM + (long)N_DIM * K_DIM + 32L * N_DIM;
    prep_kernel<<<(int)((total / 8 + 255) / 256), 256>>>(x, Ws, Wb, out);

    dim3 grid(N_DIM / BN, M_DIM / BM, KSPLIT);  // (8, 32, 4)
    gemm_kernel<<<grid, 512, SMEM_TOTAL>>>(Wd, out);
}

// round 13
// speedup vs baseline: 1.1076x; 1.1076x over previous
#include <cuda_runtime.h>
#include <cuda_fp16.h>
#include <cstdint>

// out[b,n] = sum_{c,hw} x[b,c,hw]*W_s[n,hw]*W_d[n,c] + W_b[n]
// GEMM Y[(b,c),n] = X[8192,3136] @ Ws[1024,3136]^T, single-fp16 mma.sync,
// fp32 accum, fused W_d epilogue, K-split 4 via atomicAdd merge.
// R12: scratch stored PRE-SWIZZLED in [tile][chunk][16KB] blocks; gemm loads
// each chunk with ONE cp.async.bulk per matrix (DMA engine + mbarrier)
// instead of 2048 per-thread cp.async ops -> frees issue slots for HMMA
// (R11 lesson: smem bandwidth wasn't binding; issue contention is).

#define K_DIM 3136
#define C_DIM 256
#define N_DIM 1024
#define M_DIM 8192
#define BM 128
#define BN 128
#define BK 64
#define KSPLIT 4
#define NCH_TOT 49            // 3136/64
#define BLK_B 16384           // one (tile,chunk) block: 128 rows * 128B
#define BLK_H 8192            // same in halves
#define STAGE_B 32768         // A + B
#define SMEM_TOTAL (1024 + 3 * STAGE_B)   // bars + 3 stages = 99328

// ---------------- scratch (alloc-free), tiled-swizzled layout ----------------
// g_X16: [64 m-tiles][49 chunks][8192 h], g_W16: [8 n-tiles][49 chunks][8192 h]
__device__ __align__(256) __half g_X16[(long)M_DIM * K_DIM];
__device__ __align__(256) __half g_W16[(long)N_DIM * K_DIM];

__device__ __forceinline__ uint32_t smem_u32(const void* p) {
    uint32_t a;
    asm("{ .reg .u64 t; cvta.to.shared.u64 t, %1; cvt.u32.u64 %0, t; }"
        : "=r"(a) : "l"(p));
    return a;
}
__device__ __forceinline__ void ldsm4(uint32_t& r0, uint32_t& r1, uint32_t& r2,
                                      uint32_t& r3, uint32_t a) {
    asm volatile("ldmatrix.sync.aligned.m8n8.x4.shared.b16 {%0,%1,%2,%3}, [%4];"
                 : "=r"(r0), "=r"(r1), "=r"(r2), "=r"(r3) : "r"(a));
}
__device__ __forceinline__ void mma16816(float* c, const uint32_t* a,
                                         const uint32_t* b) {
    asm volatile(
        "mma.sync.aligned.m16n8k16.row.col.f32.f16.f16.f32 "
        "{%0,%1,%2,%3}, {%4,%5,%6,%7}, {%8,%9}, {%0,%1,%2,%3};"
        : "+f"(c[0]), "+f"(c[1]), "+f"(c[2]), "+f"(c[3])
        : "r"(a[0]), "r"(a[1]), "r"(a[2]), "r"(a[3]), "r"(b[0]), "r"(b[1]));
}
__device__ __forceinline__ void bulk_ld(uint32_t dst, const void* src,
                                        uint32_t bytes, uint32_t mbar) {
    asm volatile(
        "cp.async.bulk.shared::cluster.global.mbarrier::complete_tx::bytes "
        "[%0], [%1], %2, [%3];"
        :: "r"(dst), "l"(src), "r"(bytes), "r"(mbar) : "memory");
}
#define MBAR_INIT(a, c) \
    asm volatile("mbarrier.init.shared.b64 [%0], %1;" :: "r"(a), "r"(c) : "memory")
#define MBAR_EXPECT(a, tx) \
    asm volatile("mbarrier.arrive.expect_tx.shared.b64 _, [%0], %1;" \
                 :: "r"(a), "r"(tx) : "memory")
__device__ __forceinline__ void mbar_wait(uint32_t mbar, uint32_t parity) {
    asm volatile(
        "{ .reg .pred P1;\n"
        "WL_%=:\n"
        "mbarrier.try_wait.parity.acquire.cta.shared::cta.b64 P1, [%0], %1, 0x989680;\n"
        "@P1 bra.uni WD_%=;\n"
        "bra.uni WL_%=;\n"
        "WD_%=: }"
        :: "r"(mbar), "r"(parity) : "memory");
}

// ---------------- prep: fp32 -> fp16 into tiled-swizzled blocks + bias ------
// linear index over [tiles][chunks][128 rows][8 cols-of-16B]; one 16B out each
__global__ void prep_kernel(const float* __restrict__ x,
                            const float* __restrict__ ws,
                            const float* __restrict__ wb,
                            float* __restrict__ out) {
    const long NXC = 64L * NCH_TOT * 1024;   // X: 16B-chunk count
    const long NWC = 8L * NCH_TOT * 1024;    // W: 16B-chunk count
    long i = (long)blockIdx.x * blockDim.x + threadIdx.x;
    if (i < NXC + NWC) {
        const bool isX = i < NXC;
        const long j = isX ? i : i - NXC;
        const int c = (int)(j & 7);          // 16B col within row
        const int row = (int)((j >> 3) & 127);
        const int ch = (int)((j >> 10) % NCH_TOT);
        const int tile = (int)(j / (1024L * NCH_TOT));
        const float* src = (isX ? x : ws) +
            ((long)(tile * BM + row) * K_DIM + (long)ch * BK + c * 8);
        float4 v0 = *(const float4*)src;
        float4 v1 = *(const float4*)(src + 4);
        __half2 h0 = __floats2half2_rn(v0.x, v0.y);
        __half2 h1 = __floats2half2_rn(v0.z, v0.w);
        __half2 h2 = __floats2half2_rn(v1.x, v1.y);
        __half2 h3 = __floats2half2_rn(v1.z, v1.w);
        uint4 r;
        r.x = *(const uint32_t*)&h0; r.y = *(const uint32_t*)&h1;
        r.z = *(const uint32_t*)&h2; r.w = *(const uint32_t*)&h3;
        __half* base = isX ? g_X16 : g_W16;
        const long blk = ((long)tile * NCH_TOT + ch) * BLK_H;
        const uint32_t soff =
            (uint32_t)(row * 128) + (((uint32_t)(c ^ (row & 7))) << 4);
        *(uint4*)((char*)(base + blk) + soff) = r;
    } else if (i < NXC + NWC + 4096) {       // bias: 8 floats per thread
        long j = (i - NXC - NWC) * 8;        // 0..32767
        int nb = (int)(j & (N_DIM - 1));
        float4 b0 = *(const float4*)(wb + nb);
        float4 b1 = *(const float4*)(wb + nb + 4);
        *(float4*)(out + j) = b0;
        *(float4*)(out + j + 4) = b1;
    }
}

// ---------------- main GEMM ----------------
__global__ __launch_bounds__(256, 2)
void gemm_kernel(const float* __restrict__ Wd, float* __restrict__ out) {
    extern __shared__ char smem[];
    const uint32_t sb = smem_u32(smem);
    const uint32_t stage0 = sb + 1024u;
    const int tid = threadIdx.x;
    const int lane = tid & 31;
    const int warp = tid >> 5;
    const int mt = blockIdx.y;
    const int nt = blockIdx.x;
    const int m0 = mt * BM;
    const int n0 = nt * BN;
    const int mwarp = (warp >> 2) * 64;   // 2 warp-rows
    const int nwarp = (warp & 3) * 32;    // 4 warp-cols

    // K-split range: boundaries 0,13,25,37,49
    const int z = blockIdx.z;
    const int cs = (z == 0) ? 0 : 13 + 12 * (z - 1);
    const int nch = 13 + 12 * z - cs;

    float acc[4][4][4];
#pragma unroll
    for (int i = 0; i < 4; ++i)
#pragma unroll
        for (int j = 0; j < 4; ++j)
#pragma unroll
            for (int k = 0; k < 4; ++k) acc[i][j][k] = 0.f;

    const uint32_t e = (uint32_t)(lane & 7);          // swizzle key
    const uint32_t a_row = (uint32_t)(mwarp + (lane & 15)) * 128u;
    const uint32_t b_row =
        (uint32_t)(nwarp + (lane & 7) + ((lane >> 4) & 1) * 8) * 128u;
    uint32_t akoff[4], bkoff[4];
#pragma unroll
    for (int ks = 0; ks < 4; ++ks) {
        akoff[ks] = (((uint32_t)(ks * 2 + (lane >> 4)) ^ e) << 4);
        bkoff[ks] = (((uint32_t)(ks * 2 + ((lane >> 3) & 1)) ^ e) << 4);
    }

    // producer: tid0 issues one expect_tx + two 16KB bulk copies per chunk
    const __half* srcA = g_X16 + ((long)mt * NCH_TOT + cs) * BLK_H;
    const __half* srcB = g_W16 + ((long)nt * NCH_TOT + cs) * BLK_H;
    auto issue = [&](int j) {   // local chunk j
        const uint32_t s = (uint32_t)(j % 3);
        const uint32_t mb = sb + 8u * s;
        const uint32_t st = stage0 + s * STAGE_B;
        MBAR_EXPECT(mb, (uint32_t)STAGE_B);
        bulk_ld(st, srcA + (long)j * BLK_H, BLK_B, mb);
        bulk_ld(st + BLK_B, srcB + (long)j * BLK_H, BLK_B, mb);
    };

    if (tid == 0) {
        MBAR_INIT(sb + 0, 1);
        MBAR_INIT(sb + 8, 1);
        MBAR_INIT(sb + 16, 1);
    }
    __syncthreads();
    if (tid == 0) { issue(0); issue(1); }

    for (int i = 0; i < nch; ++i) {
        mbar_wait(sb + 8u * (uint32_t)(i % 3), (uint32_t)((i / 3) & 1));
        __syncthreads();   // all warps done with chunk i-1 (stage (i+2)%3)
        if (tid == 0 && i + 2 < nch) issue(i + 2);

        const uint32_t st = stage0 + (uint32_t)(i % 3) * STAGE_B;
        const uint32_t Ab = st + a_row;
        const uint32_t Bb = st + BLK_B + b_row;
#pragma unroll
        for (int ks = 0; ks < 4; ++ks) {
            uint32_t a[4][4], b[4][2];
#pragma unroll
            for (int mi = 0; mi < 4; ++mi)
                ldsm4(a[mi][0], a[mi][1], a[mi][2], a[mi][3],
                      Ab + (uint32_t)(mi * 16 * 128) + akoff[ks]);
#pragma unroll
            for (int seg = 0; seg < 2; ++seg)
                ldsm4(b[2 * seg][0], b[2 * seg][1], b[2 * seg + 1][0],
                      b[2 * seg + 1][1],
                      Bb + (uint32_t)(seg * 16 * 128) + bkoff[ks]);
#pragma unroll
            for (int mi = 0; mi < 4; ++mi)
#pragma unroll
                for (int ni = 0; ni < 4; ++ni)
                    mma16816(acc[mi][ni], a[mi], b[ni]);
        }
    }

    // ---------------- fused epilogue (partial over this z's K range) --------
    const int b = m0 >> 8;
    const int cbase = (m0 & (C_DIM - 1)) + mwarp;
    const int g = lane >> 2;
    const int t = lane & 3;

    float p[4][2];
#pragma unroll
    for (int ni = 0; ni < 4; ++ni) { p[ni][0] = 0.f; p[ni][1] = 0.f; }

#pragma unroll
    for (int mi = 0; mi < 4; ++mi) {
        const int c0 = cbase + mi * 16 + g;
#pragma unroll
        for (int ni = 0; ni < 4; ++ni) {
            const int n = n0 + nwarp + ni * 8 + 2 * t;
#pragma unroll
            for (int j = 0; j < 2; ++j) {
                const float w0 = __ldg(Wd + (long)(n + j) * C_DIM + c0);
                const float w1 = __ldg(Wd + (long)(n + j) * C_DIM + c0 + 8);
                p[ni][j] += acc[mi][ni][j] * w0 + acc[mi][ni][j + 2] * w1;
            }
        }
    }
#pragma unroll
    for (int ni = 0; ni < 4; ++ni)
#pragma unroll
        for (int j = 0; j < 2; ++j) {
#pragma unroll
            for (int mk = 4; mk <= 16; mk <<= 1)
                p[ni][j] += __shfl_xor_sync(0xFFFFFFFFu, p[ni][j], mk);
        }
    if (lane < 4) {
#pragma unroll
        for (int ni = 0; ni < 4; ++ni)
#pragma unroll
            for (int j = 0; j < 2; ++j)
                atomicAdd(out + (long)b * N_DIM + n0 + nwarp + ni * 8 + 2 * t + j,
                          p[ni][j]);
    }
}

extern "C" void kernel_launch(void* const* d_in, const int* in_sizes, int n_in,
                              void* d_out, int out_size) {
    const float* x  = (const float*)d_in[0];  // (32,256,56,56)
    const float* Ws = (const float*)d_in[1];  // (1024,56,56)
    const float* Wd = (const float*)d_in[2];  // (1024,256,1,1)
    const float* Wb = (const float*)d_in[3];  // (1,1024)
    float* out = (float*)d_out;               // (32,1024)

    cudaFuncSetAttribute(gemm_kernel,
                         cudaFuncAttributeMaxDynamicSharedMemorySize, SMEM_TOTAL);

    const long nthreads = 64L * NCH_TOT * 1024 + 8L * NCH_TOT * 1024 + 4096;
    prep_kernel<<<(int)((nthreads + 255) / 256), 256>>>(x, Ws, Wb, out);

    dim3 grid(N_DIM / BN, M_DIM / BM, KSPLIT);  // (8, 64, 4)
    gemm_kernel<<<grid, 256, SMEM_TOTAL>>>(Wd, out);
}

// round 14
// speedup vs baseline: 1.2050x; 1.0880x over previous
#include <cuda_runtime.h>
#include <cuda_fp16.h>
#include <cstdint>

// out[b,n] = sum_{c,hw} x[b,c,hw]*W_s[n,hw]*W_d[n,c] + W_b[n]
// GEMM Y[(b,c),n] = X[8192,3136] @ Ws[1024,3136]^T, single-fp16 mma.sync,
// fp32 accum, fused W_d epilogue, K-split 4 via atomicAdd merge.
// R13: full producer/consumer mbarrier pipeline. The per-chunk __syncthreads
// is replaced by empty-stage mbarriers (count=8): each warp frees a stage as
// soon as its last ldmatrix returns, so warps skew and L1/tensor phases of
// different warps overlap (R12: co-bound at 68%/64%, barrier convoy = gap).

#define K_DIM 3136
#define C_DIM 256
#define N_DIM 1024
#define M_DIM 8192
#define BM 128
#define BN 128
#define BK 64
#define KSPLIT 4
#define NCH_TOT 49            // 3136/64
#define BLK_B 16384           // one (tile,chunk) block: 128 rows * 128B
#define BLK_H 8192            // same in halves
#define STAGE_B 32768         // A + B
#define SMEM_TOTAL (1024 + 3 * STAGE_B)   // bars + 3 stages = 99328

// ---------------- scratch (alloc-free), tiled-swizzled layout ----------------
// g_X16: [64 m-tiles][49 chunks][8192 h], g_W16: [8 n-tiles][49 chunks][8192 h]
__device__ __align__(256) __half g_X16[(long)M_DIM * K_DIM];
__device__ __align__(256) __half g_W16[(long)N_DIM * K_DIM];

__device__ __forceinline__ uint32_t smem_u32(const void* p) {
    uint32_t a;
    asm("{ .reg .u64 t; cvta.to.shared.u64 t, %1; cvt.u32.u64 %0, t; }"
        : "=r"(a) : "l"(p));
    return a;
}
__device__ __forceinline__ void ldsm4(uint32_t& r0, uint32_t& r1, uint32_t& r2,
                                      uint32_t& r3, uint32_t a) {
    asm volatile("ldmatrix.sync.aligned.m8n8.x4.shared.b16 {%0,%1,%2,%3}, [%4];"
                 : "=r"(r0), "=r"(r1), "=r"(r2), "=r"(r3) : "r"(a));
}
__device__ __forceinline__ void mma16816(float* c, const uint32_t* a,
                                         const uint32_t* b) {
    asm volatile(
        "mma.sync.aligned.m16n8k16.row.col.f32.f16.f16.f32 "
        "{%0,%1,%2,%3}, {%4,%5,%6,%7}, {%8,%9}, {%0,%1,%2,%3};"
        : "+f"(c[0]), "+f"(c[1]), "+f"(c[2]), "+f"(c[3])
        : "r"(a[0]), "r"(a[1]), "r"(a[2]), "r"(a[3]), "r"(b[0]), "r"(b[1]));
}
__device__ __forceinline__ void bulk_ld(uint32_t dst, const void* src,
                                        uint32_t bytes, uint32_t mbar) {
    asm volatile(
        "cp.async.bulk.shared::cluster.global.mbarrier::complete_tx::bytes "
        "[%0], [%1], %2, [%3];"
        :: "r"(dst), "l"(src), "r"(bytes), "r"(mbar) : "memory");
}
#define MBAR_INIT(a, c) \
    asm volatile("mbarrier.init.shared.b64 [%0], %1;" :: "r"(a), "r"(c) : "memory")
#define MBAR_EXPECT(a, tx) \
    asm volatile("mbarrier.arrive.expect_tx.shared.b64 _, [%0], %1;" \
                 :: "r"(a), "r"(tx) : "memory")
#define MBAR_ARRIVE(a) \
    asm volatile("mbarrier.arrive.shared.b64 _, [%0];" :: "r"(a) : "memory")
__device__ __forceinline__ void mbar_wait(uint32_t mbar, uint32_t parity) {
    asm volatile(
        "{ .reg .pred P1;\n"
        "WL_%=:\n"
        "mbarrier.try_wait.parity.acquire.cta.shared::cta.b64 P1, [%0], %1, 0x989680;\n"
        "@P1 bra.uni WD_%=;\n"
        "bra.uni WL_%=;\n"
        "WD_%=: }"
        :: "r"(mbar), "r"(parity) : "memory");
}

// ---------------- prep: fp32 -> fp16 into tiled-swizzled blocks + bias ------
__global__ void prep_kernel(const float* __restrict__ x,
                            const float* __restrict__ ws,
                            const float* __restrict__ wb,
                            float* __restrict__ out) {
    const long NXC = 64L * NCH_TOT * 1024;   // X: 16B-chunk count
    const long NWC = 8L * NCH_TOT * 1024;    // W: 16B-chunk count
    long i = (long)blockIdx.x * blockDim.x + threadIdx.x;
    if (i < NXC + NWC) {
        const bool isX = i < NXC;
        const long j = isX ? i : i - NXC;
        const int c = (int)(j & 7);          // 16B col within row
        const int row = (int)((j >> 3) & 127);
        const int ch = (int)((j >> 10) % NCH_TOT);
        const int tile = (int)(j / (1024L * NCH_TOT));
        const float* src = (isX ? x : ws) +
            ((long)(tile * BM + row) * K_DIM + (long)ch * BK + c * 8);
        float4 v0 = *(const float4*)src;
        float4 v1 = *(const float4*)(src + 4);
        __half2 h0 = __floats2half2_rn(v0.x, v0.y);
        __half2 h1 = __floats2half2_rn(v0.z, v0.w);
        __half2 h2 = __floats2half2_rn(v1.x, v1.y);
        __half2 h3 = __floats2half2_rn(v1.z, v1.w);
        uint4 r;
        r.x = *(const uint32_t*)&h0; r.y = *(const uint32_t*)&h1;
        r.z = *(const uint32_t*)&h2; r.w = *(const uint32_t*)&h3;
        __half* base = isX ? g_X16 : g_W16;
        const long blk = ((long)tile * NCH_TOT + ch) * BLK_H;
        const uint32_t soff =
            (uint32_t)(row * 128) + (((uint32_t)(c ^ (row & 7))) << 4);
        *(uint4*)((char*)(base + blk) + soff) = r;
    } else if (i < NXC + NWC + 4096) {       // bias: 8 floats per thread
        long j = (i - NXC - NWC) * 8;        // 0..32767
        int nb = (int)(j & (N_DIM - 1));
        float4 b0 = *(const float4*)(wb + nb);
        float4 b1 = *(const float4*)(wb + nb + 4);
        *(float4*)(out + j) = b0;
        *(float4*)(out + j + 4) = b1;
    }
}

// ---------------- main GEMM ----------------
// barriers: full[s] at sb+8s (count 1, tx), empty[s] at sb+24+8s (count 8).
__global__ __launch_bounds__(256, 2)
void gemm_kernel(const float* __restrict__ Wd, float* __restrict__ out) {
    extern __shared__ char smem[];
    const uint32_t sb = smem_u32(smem);
    const uint32_t stage0 = sb + 1024u;
    const int tid = threadIdx.x;
    const int lane = tid & 31;
    const int warp = tid >> 5;
    const int mt = blockIdx.y;
    const int nt = blockIdx.x;
    const int m0 = mt * BM;
    const int n0 = nt * BN;
    const int mwarp = (warp >> 2) * 64;   // 2 warp-rows
    const int nwarp = (warp & 3) * 32;    // 4 warp-cols

    // K-split range: boundaries 0,13,25,37,49
    const int z = blockIdx.z;
    const int cs = (z == 0) ? 0 : 13 + 12 * (z - 1);
    const int nch = 13 + 12 * z - cs;

    float acc[4][4][4];
#pragma unroll
    for (int i = 0; i < 4; ++i)
#pragma unroll
        for (int j = 0; j < 4; ++j)
#pragma unroll
            for (int k = 0; k < 4; ++k) acc[i][j][k] = 0.f;

    const uint32_t e = (uint32_t)(lane & 7);          // swizzle key
    const uint32_t a_row = (uint32_t)(mwarp + (lane & 15)) * 128u;
    const uint32_t b_row =
        (uint32_t)(nwarp + (lane & 7) + ((lane >> 4) & 1) * 8) * 128u;
    uint32_t akoff[4], bkoff[4];
#pragma unroll
    for (int ks = 0; ks < 4; ++ks) {
        akoff[ks] = (((uint32_t)(ks * 2 + (lane >> 4)) ^ e) << 4);
        bkoff[ks] = (((uint32_t)(ks * 2 + ((lane >> 3) & 1)) ^ e) << 4);
    }

    // producer: tid0 waits empty, then expect_tx + two 16KB bulk copies
    const __half* srcA = g_X16 + ((long)mt * NCH_TOT + cs) * BLK_H;
    const __half* srcB = g_W16 + ((long)nt * NCH_TOT + cs) * BLK_H;
    auto issue = [&](int j) {   // local chunk j
        const uint32_t s = (uint32_t)(j % 3);
        mbar_wait(sb + 24u + 8u * s, (uint32_t)((j / 3 + 1) & 1));
        const uint32_t mb = sb + 8u * s;
        const uint32_t st = stage0 + s * STAGE_B;
        MBAR_EXPECT(mb, (uint32_t)STAGE_B);
        bulk_ld(st, srcA + (long)j * BLK_H, BLK_B, mb);
        bulk_ld(st + BLK_B, srcB + (long)j * BLK_H, BLK_B, mb);
    };

    if (tid == 0) {
        MBAR_INIT(sb + 0, 1);    // full[0..2]
        MBAR_INIT(sb + 8, 1);
        MBAR_INIT(sb + 16, 1);
        MBAR_INIT(sb + 24, 8);   // empty[0..2]: one arrive per warp
        MBAR_INIT(sb + 32, 8);
        MBAR_INIT(sb + 40, 8);
    }
    __syncthreads();
    if (tid == 0) { issue(0); issue(1); }

    for (int i = 0; i < nch; ++i) {
        const uint32_t s = (uint32_t)(i % 3);
        mbar_wait(sb + 8u * s, (uint32_t)((i / 3) & 1));   // full[s]
        if (tid == 0 && i + 2 < nch) issue(i + 2);

        const uint32_t st = stage0 + s * STAGE_B;
        const uint32_t Ab = st + a_row;
        const uint32_t Bb = st + BLK_B + b_row;
#pragma unroll
        for (int ks = 0; ks < 4; ++ks) {
            uint32_t a[4][4], b[4][2];
#pragma unroll
            for (int mi = 0; mi < 4; ++mi)
                ldsm4(a[mi][0], a[mi][1], a[mi][2], a[mi][3],
                      Ab + (uint32_t)(mi * 16 * 128) + akoff[ks]);
#pragma unroll
            for (int seg = 0; seg < 2; ++seg)
                ldsm4(b[2 * seg][0], b[2 * seg][1], b[2 * seg + 1][0],
                      b[2 * seg + 1][1],
                      Bb + (uint32_t)(seg * 16 * 128) + bkoff[ks]);
            if (ks == 3 && lane == 0)
                MBAR_ARRIVE(sb + 24u + 8u * s);  // stage free: regs hold data
#pragma unroll
            for (int mi = 0; mi < 4; ++mi)
#pragma unroll
                for (int ni = 0; ni < 4; ++ni)
                    mma16816(acc[mi][ni], a[mi], b[ni]);
        }
    }

    // ---------------- fused epilogue (partial over this z's K range) --------
    const int b = m0 >> 8;
    const int cbase = (m0 & (C_DIM - 1)) + mwarp;
    const int g = lane >> 2;
    const int t = lane & 3;

    float p[4][2];
#pragma unroll
    for (int ni = 0; ni < 4; ++ni) { p[ni][0] = 0.f; p[ni][1] = 0.f; }

#pragma unroll
    for (int mi = 0; mi < 4; ++mi) {
        const int c0 = cbase + mi * 16 + g;
#pragma unroll
        for (int ni = 0; ni < 4; ++ni) {
            const int n = n0 + nwarp + ni * 8 + 2 * t;
#pragma unroll
            for (int j = 0; j < 2; ++j) {
                const float w0 = __ldg(Wd + (long)(n + j) * C_DIM + c0);
                const float w1 = __ldg(Wd + (long)(n + j) * C_DIM + c0 + 8);
                p[ni][j] += acc[mi][ni][j] * w0 + acc[mi][ni][j + 2] * w1;
            }
        }
    }
#pragma unroll
    for (int ni = 0; ni < 4; ++ni)
#pragma unroll
        for (int j = 0; j < 2; ++j) {
#pragma unroll
            for (int mk = 4; mk <= 16; mk <<= 1)
                p[ni][j] += __shfl_xor_sync(0xFFFFFFFFu, p[ni][j], mk);
        }
    if (lane < 4) {
#pragma unroll
        for (int ni = 0; ni < 4; ++ni)
#pragma unroll
            for (int j = 0; j < 2; ++j)
                atomicAdd(out + (long)b * N_DIM + n0 + nwarp + ni * 8 + 2 * t + j,
                          p[ni][j]);
    }
}

extern "C" void kernel_launch(void* const* d_in, const int* in_sizes, int n_in,
                              void* d_out, int out_size) {
    const float* x  = (const float*)d_in[0];  // (32,256,56,56)
    const float* Ws = (const float*)d_in[1];  // (1024,56,56)
    const float* Wd = (const float*)d_in[2];  // (1024,256,1,1)
    const float* Wb = (const float*)d_in[3];  // (1,1024)
    float* out = (float*)d_out;               // (32,1024)

    cudaFuncSetAttribute(gemm_kernel,
                         cudaFuncAttributeMaxDynamicSharedMemorySize, SMEM_TOTAL);

    const long nthreads = 64L * NCH_TOT * 1024 + 8L * NCH_TOT * 1024 + 4096;
    prep_kernel<<<(int)((nthreads + 255) / 256), 256>>>(x, Ws, Wb, out);

    dim3 grid(N_DIM / BN, M_DIM / BM, KSPLIT);  // (8, 64, 4)
    gemm_kernel<<<grid, 256, SMEM_TOTAL>>>(Wd, out);
}